// round 10
// baseline (speedup 1.0000x reference)
#include <cuda_runtime.h>

// Problem constants
#define B 32
#define C 3
#define Hh 640
#define Ww 640
#define POOLN 8
#define CELL 80
#define HIDDEN 64
#define FEAT 192             // C*POOLN*POOLN
#define NPARAM 15
#define PLANE (Hh*Ww)        // 409600
#define PLANE4 (PLANE/4)     // 102400
#define W4 (Ww/4)            // 160

// Work queue layout
#define PUNITS_PER_IMG 96    // 24 bands x 4 row-quarters
#define NPOOL (B*PUNITS_PER_IMG)       // 3072
#define TCH 320              // transform chunks per image (PLANE4/320)
#define NTRANS (B*TCH)                 // 10240
#define NITEMS (NPOOL + NTRANS)        // 13312
#define LEAD 4               // pool leads transform by 4 images
#define NTHREADS 320
#define GRID 592             // ~4 blocks/SM on 148 SMs (queue is safe if fewer resident)

// Scratch / sync state (allocation-free rule: __device__ globals)
__device__ int   g_head;
__device__ int   g_cnt[B];
__device__ int   g_flag[B];
__device__ float g_partial[B * FEAT * 4];
__device__ float g_params[B * 32];     // padded to 128B/image (avoids cross-image L1 line sharing)

// ---------------------------------------------------------------------------
__global__ void init_kernel() {
    if (threadIdx.x == 0) g_head = 0;
    if (threadIdx.x < B) { g_cnt[threadIdx.x] = 0; g_flag[threadIdx.x] = 0; }
}

// ---------------------------------------------------------------------------
// Persistent fused kernel: pool + inline MLP + transform via ordered queue.
// Deadlock-free: spins only wait on queue-earlier items; queue-earlier items
// are wait-free pool units that always complete.
// ---------------------------------------------------------------------------
__global__ __launch_bounds__(NTHREADS) void fused_kernel(
    const float* __restrict__ x,  const float* __restrict__ W1,
    const float* __restrict__ b1, const float* __restrict__ W2,
    float* __restrict__ out)
{
    __shared__ int   s_item;
    __shared__ int   s_domlp;
    __shared__ float sred[NTHREADS];   // pool reduce; reused as fs[192] in MLP
    __shared__ float hsm[HIDDEN];
    __shared__ float psm[16];
    const int tid = threadIdx.x;

    for (;;) {
        if (tid == 0) s_item = atomicAdd(&g_head, 1);
        __syncthreads();
        const int n = s_item;
        if (n >= NITEMS) return;

        // ---- decode interleaved schedule ----
        // [pool img0-3 (384)] then 28 groups of [trans imgK (320) | pool imgK+4 (96)]
        // then [trans img28-31 (1280)]
        int pool_unit = -1, timg = -1, tchunk = -1;
        if (n < LEAD * PUNITS_PER_IMG) {
            pool_unit = n;
        } else {
            int m   = n - LEAD * PUNITS_PER_IMG;
            int grp = m / (TCH + PUNITS_PER_IMG);          // /416
            int r   = m - grp * (TCH + PUNITS_PER_IMG);
            if (grp < B - LEAD) {
                if (r < TCH) { timg = grp; tchunk = r; }
                else         { pool_unit = (grp + LEAD) * PUNITS_PER_IMG + (r - TCH); }
            } else {
                int r2 = n - (LEAD * PUNITS_PER_IMG + (B - LEAD) * (TCH + PUNITS_PER_IMG));
                timg   = (B - LEAD) + r2 / TCH;
                tchunk = r2 - (r2 / TCH) * TCH;
            }
        }

        if (pool_unit >= 0) {
            // ================= POOL UNIT: (b,c,pr,quarter) 20 rows x 640 cols ====
            const int b    = pool_unit / PUNITS_PER_IMG;
            const int rr   = pool_unit - b * PUNITS_PER_IMG;
            const int band = rr >> 2;          // c*8 + pr
            const int q    = rr & 3;
            const int c    = band >> 3;
            const int pr   = band & 7;
            const int rg   = tid / 160;        // row group (10 rows each)
            const int col  = tid - rg * 160;   // float4 column

            const float4* p = (const float4*)x
                + ((size_t)(b * C + c) * Hh + (size_t)(pr * CELL + q * 20 + rg * 10)) * W4
                + col;
            float4 a0 = make_float4(0.f,0.f,0.f,0.f);
            float4 a1 = make_float4(0.f,0.f,0.f,0.f);
            #pragma unroll
            for (int i = 0; i < 10; i += 2) {
                float4 v0 = p[(size_t)i * W4];
                float4 v1 = p[(size_t)(i + 1) * W4];
                a0.x += v0.x; a0.y += v0.y; a0.z += v0.z; a0.w += v0.w;
                a1.x += v1.x; a1.y += v1.y; a1.z += v1.z; a1.w += v1.w;
            }
            sred[tid] = (a0.x + a0.y + a0.z + a0.w) + (a1.x + a1.y + a1.z + a1.w);
            __syncthreads();

            if (tid < POOLN) {                 // 8 pool cols, 20 f4-cols x 2 rowgrps
                float t = 0.f;
                #pragma unroll
                for (int j = 0; j < 20; ++j)
                    t += sred[tid * 20 + j] + sred[160 + tid * 20 + j];
                __stcg(&g_partial[((size_t)b * FEAT + (c * 64 + pr * 8 + tid)) * 4 + q], t);
            }
            __syncthreads();
            if (tid == 0) {
                __threadfence();
                s_domlp = (atomicAdd(&g_cnt[b], 1) == PUNITS_PER_IMG - 1);
            }
            __syncthreads();

            if (s_domlp) {
                // ---- inline MLP for image b (last pool unit finisher) ----
                __threadfence();               // acquire side
                if (tid < HIDDEN) {
                    for (int k = tid; k < FEAT; k += HIDDEN) {
                        const float* pp = &g_partial[((size_t)b * FEAT + k) * 4];
                        sred[k] = (__ldcg(pp) + __ldcg(pp+1) + __ldcg(pp+2) + __ldcg(pp+3))
                                  * (1.f / (CELL * CELL));
                    }
                }
                __syncthreads();
                if (tid < HIDDEN) {
                    float acc = b1[tid];
                    #pragma unroll 8
                    for (int k = 0; k < FEAT; ++k)
                        acc = fmaf(sred[k], W1[k * HIDDEN + tid], acc);
                    hsm[tid] = fminf(fmaxf(acc, 0.f), 6.f);
                }
                __syncthreads();
                if (tid < NPARAM) {
                    float a = 0.f;
                    #pragma unroll 8
                    for (int k = 0; k < HIDDEN; ++k)
                        a = fmaf(hsm[k], W2[k * NPARAM + tid], a);
                    __stcg(&g_params[b * 32 + tid], 1.f / (1.f + __expf(-a)));
                }
                __syncthreads();
                if (tid == 0) { __threadfence(); atomicExch(&g_flag[b], 1); }
            }
        } else {
            // ================= TRANSFORM ITEM: 320 float4/channel ================
            if (tid == 0) {
                volatile int* vf = g_flag + timg;
                while (*vf == 0) __nanosleep(128);
                __threadfence();               // acquire
            }
            __syncthreads();
            if (tid < 16) psm[tid] = __ldcg(&g_params[timg * 32 + tid]);
            __syncthreads();

            const float m00 = psm[0], m01 = psm[1], m02 = psm[2];
            const float m10 = psm[3], m11 = psm[4], m12 = psm[5];
            const float m20 = psm[6], m21 = psm[7], m22 = psm[8];
            const float bi0 = psm[9], bi1 = psm[10], bi2 = psm[11];
            const float g0  = psm[12], g1 = psm[13], g2 = psm[14];
            const float s0 = 1.0f/0.229f, s1 = 1.0f/0.224f, s2 = 1.0f/0.225f;
            const float t0 = -0.485f/0.229f, t1 = -0.456f/0.224f, t2 = -0.406f/0.225f;

            const int i4 = tchunk * TCH + tid;          // 0..PLANE4-1
            const float4* xb = (const float4*)x + (size_t)timg * C * PLANE4;
            float4* ob = (float4*)out + (size_t)timg * C * PLANE4;

            float4 xa = xb[i4];
            float4 xc = xb[i4 + PLANE4];
            float4 xd = xb[i4 + 2 * PLANE4];

            float4 o0, o1, o2;
            #define DO_ELEM(FLD)                                                       \
            {                                                                          \
                float a = xa.FLD, bch = xc.FLD, cch = xd.FLD;                          \
                float y0 = fmaf(m00, a, fmaf(m01, bch, fmaf(m02, cch, bi0)));          \
                float y1 = fmaf(m10, a, fmaf(m11, bch, fmaf(m12, cch, bi1)));          \
                float y2 = fmaf(m20, a, fmaf(m21, bch, fmaf(m22, cch, bi2)));          \
                y0 = fmaxf(y0, 1e-20f); y1 = fmaxf(y1, 1e-20f); y2 = fmaxf(y2, 1e-20f);\
                o0.FLD = fmaf(__powf(y0, g0), s0, t0);                                 \
                o1.FLD = fmaf(__powf(y1, g1), s1, t1);                                 \
                o2.FLD = fmaf(__powf(y2, g2), s2, t2);                                 \
            }
            DO_ELEM(x) DO_ELEM(y) DO_ELEM(z) DO_ELEM(w)
            #undef DO_ELEM

            __stcs(ob + i4,              o0);
            __stcs(ob + i4 + PLANE4,     o1);
            __stcs(ob + i4 + 2 * PLANE4, o2);
        }
        __syncthreads();   // protect smem (s_item/sred/psm) before next iteration
    }
}

// ---------------------------------------------------------------------------
extern "C" void kernel_launch(void* const* d_in, const int* in_sizes, int n_in,
                              void* d_out, int out_size) {
    const float* x  = (const float*)d_in[0];   // (32,3,640,640)
    const float* W1 = (const float*)d_in[1];   // (192,64)
    const float* b1 = (const float*)d_in[2];   // (64,)
    const float* W2 = (const float*)d_in[3];   // (64,15)
    float* out = (float*)d_out;

    init_kernel<<<1, 64>>>();
    fused_kernel<<<GRID, NTHREADS>>>(x, W1, b1, W2, out);
}

// round 12
// speedup vs baseline: 1.4769x; 1.4769x over previous
#include <cuda_runtime.h>

// Problem constants
#define B 32
#define C 3
#define Hh 640
#define Ww 640
#define POOLN 8
#define CELL 80
#define HIDDEN 64
#define FEAT 192             // C*POOLN*POOLN
#define NPARAM 15
#define PLANE (Hh*Ww)        // 409600
#define PLANE4 (PLANE/4)     // 102400
#define W4 (Ww/4)            // 160

#define PUNITS_PER_IMG 96    // 24 bands x 4 row-quarters
#define POOL_BLOCKS (B * PUNITS_PER_IMG)   // 3072

// Transform: 4 float4-groups per thread, 256 threads -> 1024 f4/channel/block
#define TGROUPS 4
#define TBLOCK 256
#define F4_PER_BLK (TBLOCK * TGROUPS)      // 1024
#define TCHUNKS (PLANE4 / F4_PER_BLK)      // 100
#define TRANS_BLOCKS (B * TCHUNKS)         // 3200

// Scratch / sync state (allocation-free rule: __device__ globals)
__device__ int   g_cnt[B];                 // zero-init; finisher resets -> replay-safe
__device__ float g_partial[B * FEAT * 4];
__device__ float g_params[B * 32];         // padded to 128B/image

// ---------------------------------------------------------------------------
// Kernel 1: pool + inline MLP (last-finisher). 3072 blocks x 160 threads.
// Thread j sums 20 rows of float4-column j (fully coalesced), block reduces
// to 8 pool-col partials. The 96th finishing block for an image runs the
// MLP inline and resets the counter (graph-replay determinism).
// ---------------------------------------------------------------------------
__global__ __launch_bounds__(160) void pool_mlp_kernel(
    const float* __restrict__ x,  const float* __restrict__ W1,
    const float* __restrict__ b1, const float* __restrict__ W2)
{
    const int blk  = blockIdx.x;         // 0 .. 3071
    const int b    = blk / PUNITS_PER_IMG;
    const int bq   = blk - b * PUNITS_PER_IMG;
    const int band = bq >> 2;            // 0..23 = c*8 + pr
    const int q    = bq & 3;             // row quarter (20 rows)
    const int c    = band >> 3;
    const int pr   = band & 7;
    const int tid  = threadIdx.x;

    const float4* p = (const float4*)x
        + ((size_t)(b * C + c) * Hh + (size_t)(pr * CELL + q * 20)) * W4
        + tid;

    float4 a0 = make_float4(0.f,0.f,0.f,0.f);
    float4 a1 = make_float4(0.f,0.f,0.f,0.f);
    #pragma unroll
    for (int r = 0; r < 20; r += 2) {
        float4 v0 = p[(size_t)r * W4];
        float4 v1 = p[(size_t)(r + 1) * W4];
        a0.x += v0.x; a0.y += v0.y; a0.z += v0.z; a0.w += v0.w;
        a1.x += v1.x; a1.y += v1.y; a1.z += v1.z; a1.w += v1.w;
    }

    __shared__ float sred[160];
    __shared__ float fs[FEAT];
    __shared__ float hs[HIDDEN];
    __shared__ int   s_domlp;

    sred[tid] = (a0.x + a0.y + a0.z + a0.w) + (a1.x + a1.y + a1.z + a1.w);
    __syncthreads();

    if (tid < POOLN) {                   // 8 pool cols, 20 float4-cols each
        float t = 0.f;
        #pragma unroll
        for (int j = 0; j < 20; ++j) t += sred[tid * 20 + j];
        __stcg(&g_partial[((size_t)b * FEAT + (c * 64 + pr * 8 + tid)) * 4 + q], t);
    }
    __syncthreads();
    if (tid == 0) {
        __threadfence();
        s_domlp = (atomicAdd(&g_cnt[b], 1) == PUNITS_PER_IMG - 1);
    }
    __syncthreads();

    if (s_domlp) {
        __threadfence();                 // acquire: see all 96 units' partials
        if (tid < HIDDEN) {
            for (int k = tid; k < FEAT; k += HIDDEN) {
                const float* pp = &g_partial[((size_t)b * FEAT + k) * 4];
                fs[k] = (__ldcg(pp) + __ldcg(pp+1) + __ldcg(pp+2) + __ldcg(pp+3))
                        * (1.f / (CELL * CELL));
            }
        }
        __syncthreads();
        if (tid < HIDDEN) {
            float acc = b1[tid];
            #pragma unroll 8
            for (int k = 0; k < FEAT; ++k)
                acc = fmaf(fs[k], W1[k * HIDDEN + tid], acc);
            hs[tid] = fminf(fmaxf(acc, 0.f), 6.f);
        }
        __syncthreads();
        if (tid < NPARAM) {
            float a = 0.f;
            #pragma unroll 8
            for (int k = 0; k < HIDDEN; ++k)
                a = fmaf(hs[k], W2[k * NPARAM + tid], a);
            __stcg(&g_params[b * 32 + tid], 1.f / (1.f + __expf(-a)));
        }
        if (tid == 0) g_cnt[b] = 0;      // reset for next graph replay
    }
}

// ---------------------------------------------------------------------------
// Kernel 2: transform — 4 float4-groups/thread, ALL 12 loads issued before
// any pow math (MLP=12). __stcs evict-first stores. 3200 blocks x 256 thr.
// ---------------------------------------------------------------------------
__global__ __launch_bounds__(TBLOCK) void transform_kernel(
    const float* __restrict__ x, float* __restrict__ out)
{
    const int b   = blockIdx.x / TCHUNKS;
    const int blk = blockIdx.x - b * TCHUNKS;

    __shared__ float psm[16];
    if (threadIdx.x < 16) psm[threadIdx.x] = __ldcg(&g_params[b * 32 + threadIdx.x]);
    __syncthreads();

    const float m00 = psm[0], m01 = psm[1], m02 = psm[2];
    const float m10 = psm[3], m11 = psm[4], m12 = psm[5];
    const float m20 = psm[6], m21 = psm[7], m22 = psm[8];
    const float bi0 = psm[9], bi1 = psm[10], bi2 = psm[11];
    const float g0  = psm[12], g1 = psm[13], g2 = psm[14];
    const float s0 = 1.0f/0.229f, s1 = 1.0f/0.224f, s2 = 1.0f/0.225f;
    const float t0 = -0.485f/0.229f, t1 = -0.456f/0.224f, t2 = -0.406f/0.225f;

    const int base = blk * F4_PER_BLK + threadIdx.x;
    const float4* xb = (const float4*)x + (size_t)b * C * PLANE4;
    float4* ob = (float4*)out + (size_t)b * C * PLANE4;

    // ---- issue all 12 loads up front ----
    float4 xa[TGROUPS], xc[TGROUPS], xd[TGROUPS];
    #pragma unroll
    for (int g = 0; g < TGROUPS; ++g) {
        int i4 = base + g * TBLOCK;
        xa[g] = xb[i4];
        xc[g] = xb[i4 + PLANE4];
        xd[g] = xb[i4 + 2 * PLANE4];
    }

    #pragma unroll
    for (int g = 0; g < TGROUPS; ++g) {
        float4 o0, o1, o2;
        #define DO_ELEM(FLD)                                                       \
        {                                                                          \
            float a = xa[g].FLD, bch = xc[g].FLD, cch = xd[g].FLD;                 \
            float y0 = fmaf(m00, a, fmaf(m01, bch, fmaf(m02, cch, bi0)));          \
            float y1 = fmaf(m10, a, fmaf(m11, bch, fmaf(m12, cch, bi1)));          \
            float y2 = fmaf(m20, a, fmaf(m21, bch, fmaf(m22, cch, bi2)));          \
            y0 = fmaxf(y0, 1e-20f); y1 = fmaxf(y1, 1e-20f); y2 = fmaxf(y2, 1e-20f);\
            o0.FLD = fmaf(__powf(y0, g0), s0, t0);                                 \
            o1.FLD = fmaf(__powf(y1, g1), s1, t1);                                 \
            o2.FLD = fmaf(__powf(y2, g2), s2, t2);                                 \
        }
        DO_ELEM(x) DO_ELEM(y) DO_ELEM(z) DO_ELEM(w)
        #undef DO_ELEM
        int i4 = base + g * TBLOCK;
        __stcs(ob + i4,              o0);
        __stcs(ob + i4 + PLANE4,     o1);
        __stcs(ob + i4 + 2 * PLANE4, o2);
    }
}

// ---------------------------------------------------------------------------
extern "C" void kernel_launch(void* const* d_in, const int* in_sizes, int n_in,
                              void* d_out, int out_size) {
    const float* x  = (const float*)d_in[0];   // (32,3,640,640)
    const float* W1 = (const float*)d_in[1];   // (192,64)
    const float* b1 = (const float*)d_in[2];   // (64,)
    const float* W2 = (const float*)d_in[3];   // (64,15)
    float* out = (float*)d_out;

    pool_mlp_kernel<<<POOL_BLOCKS, 160>>>(x, W1, b1, W2);
    transform_kernel<<<TRANS_BLOCKS, TBLOCK>>>(x, out);
}